// round 14
// baseline (speedup 1.0000x reference)
#include <cuda_runtime.h>
#include <math.h>
#include <stdint.h>

#define TT 262144
#define S 128
#define F 16
#define G 4             // streams per CTA
#define GRID 296        // CTAs
#define CH (G * GRID)   // 1184 chunks
#define L 222           // 1184 * 222 = 262848 >= TT (chunks 1181+ dead)
#define W 64            // warmup steps (forgetting window)
#define NZ 4            // renormalize every NZ steps
#define PF 8            // staged rows per block

// ---------------- scratch (device globals; no allocation allowed) ----------------
__device__ float g_expB[(size_t)TT * S];       // exp(logB - mB) per row, 134 MB
__device__ float g_mB[TT];                     // per-row max of logB
__device__ float g_E[S * S];                   // row-stochastic softmax(trans)
__device__ float g_pstart[S];                  // exp(log_softmax(start))
__device__ float g_iv[S * F];
__device__ float g_m2[S * F];
__device__ float g_cst[S];
__device__ float g_junc[(CH + 1) * S];         // linear junction vectors
__device__ float g_joff[CH + 1];               // offsets at junctions
__device__ float g_rl[TT];                     // per-row accumulated offset (chunk frame)
__device__ float g_dloc[CH];
__device__ float g_delta[CH];

// ---------------- packed f32x2 + cp.async helpers ----------------
#define FMA2(d, a, b, c) \
    asm("fma.rn.f32x2 %0, %1, %2, %3;" : "=l"(d) : "l"(a), "l"(b), "l"(c))
#define PACK2(d, lo, hi) \
    asm("mov.b64 %0, {%1, %2};" : "=l"(d) : "f"(lo), "f"(hi))
#define UNPK2(lo, hi, p) \
    asm("mov.b64 {%0, %1}, %2;" : "=f"(lo), "=f"(hi) : "l"(p))

__device__ __forceinline__ void cp_async16(void* smem_dst, const void* gmem_src) {
    unsigned sa = (unsigned)__cvta_generic_to_shared(smem_dst);
    asm volatile("cp.async.cg.shared.global [%0], [%1], 16;" :: "r"(sa), "l"(gmem_src));
}
__device__ __forceinline__ void cp_async4(void* smem_dst, const void* gmem_src) {
    unsigned sa = (unsigned)__cvta_generic_to_shared(smem_dst);
    asm volatile("cp.async.ca.shared.global [%0], [%1], 4;" :: "r"(sa), "l"(gmem_src));
}
__device__ __forceinline__ void cp_commit() { asm volatile("cp.async.commit_group;"); }
__device__ __forceinline__ void cp_wait0()  { asm volatile("cp.async.wait_group 0;"); }

// ---------------- fast math (FMA polys; no MUFU) ----------------
__device__ __forceinline__ float fexp_poly(float x) {
    x = fmaxf(x, -80.0f);
    float y = x * 1.44269504f;
    float n = rintf(y);
    float t = (y - n) * 0.69314718f;
    float p = 1.0f / 720.0f;
    p = fmaf(p, t, 1.0f / 120.0f);
    p = fmaf(p, t, 1.0f / 24.0f);
    p = fmaf(p, t, 1.0f / 6.0f);
    p = fmaf(p, t, 0.5f);
    p = fmaf(p, t, 1.0f);
    p = fmaf(p, t, 1.0f);
    return p * __int_as_float(((int)n + 127) << 23);
}

__device__ __forceinline__ float flog_poly(float v) {
    v = fmaxf(v, 1e-38f);
    int b = __float_as_int(v);
    int e = ((b >> 23) & 255) - 127;
    float m = __int_as_float((b & 0x007fffff) | 0x3f800000);  // [1,2)
    if (m > 1.41421356f) { m *= 0.5f; e += 1; }
    float r = m - 1.0f;
    float p = -1.0f / 12.0f;
    p = fmaf(p, r,  1.0f / 11.0f);
    p = fmaf(p, r, -1.0f / 10.0f);
    p = fmaf(p, r,  1.0f / 9.0f);
    p = fmaf(p, r, -1.0f / 8.0f);
    p = fmaf(p, r,  1.0f / 7.0f);
    p = fmaf(p, r, -1.0f / 6.0f);
    p = fmaf(p, r,  1.0f / 5.0f);
    p = fmaf(p, r, -0.25f);
    p = fmaf(p, r,  1.0f / 3.0f);
    p = fmaf(p, r, -0.5f);
    p = fmaf(p, r,  1.0f);
    return fmaf((float)e, 0.69314718f, r * p);
}

// ---------------- kernel 1: small preprocessing ----------------
__global__ void prep_kernel(const float* __restrict__ start_prob,
                            const float* __restrict__ trans,
                            const float* __restrict__ means,
                            const float* __restrict__ vars) {
    int s = threadIdx.x;  // 128 threads
    __shared__ float red[S];

    float sp = start_prob[s];
    red[s] = sp; __syncthreads();
    for (int o = 64; o > 0; o >>= 1) { if (s < o) red[s] = fmaxf(red[s], red[s + o]); __syncthreads(); }
    float mx = red[0]; __syncthreads();
    red[s] = expf(sp - mx); __syncthreads();
    for (int o = 64; o > 0; o >>= 1) { if (s < o) red[s] += red[s + o]; __syncthreads(); }
    float lse = mx + logf(red[0]);
    g_pstart[s] = expf(sp - lse);

    float m = -INFINITY;
    for (int j = 0; j < S; j++) m = fmaxf(m, trans[s * S + j]);
    float z = 0.f;
    for (int j = 0; j < S; j++) z += expf(trans[s * S + j] - m);
    float inv = 1.0f / z;
    for (int j = 0; j < S; j++) g_E[s * S + j] = expf(trans[s * S + j] - m) * inv;

    float ln = 0.f, c2 = 0.f;
    for (int f = 0; f < F; f++) {
        float v = vars[s * F + f];
        v = fmaxf(v, 1e-6f);
        float iv = 1.0f / v;
        float mu = means[s * F + f];
        g_iv[s * F + f] = iv;
        g_m2[s * F + f] = 2.0f * mu * iv;
        ln += logf(6.2831853071795864f * v);
        c2 += mu * mu * iv;
    }
    g_cst[s] = -0.5f * (ln + c2);
}

// ---------------- kernel 2: emissions -> expB + mB ----------------
#define LB_STRIDE 130
__global__ void logb_kernel(const float* __restrict__ x) {
    int s = threadIdx.x;             // 128 threads (= states)
    int t0 = blockIdx.x * 64;        // 64 timesteps per block
    __shared__ float sx[64 * F];
    __shared__ float slb[64 * LB_STRIDE];
    __shared__ float smB[64];

    for (int i = s; i < 64 * F; i += S) sx[i] = x[(size_t)t0 * F + i];
    float iv[F], m2[F];
#pragma unroll
    for (int f = 0; f < F; f++) { iv[f] = g_iv[s * F + f]; m2[f] = g_m2[s * F + f]; }
    float cst = g_cst[s];
    __syncthreads();

    for (int t = 0; t < 64; t++) {
        float q = 0.f;
#pragma unroll
        for (int f = 0; f < F; f++) {
            float xv = sx[t * F + f];
            q = fmaf(xv, fmaf(xv, iv[f], -m2[f]), q);
        }
        slb[t * LB_STRIDE + s] = cst - 0.5f * q;
    }
    __syncthreads();

    {
        int t = s >> 1, half = s & 1;
        float mx = -INFINITY;
        const float* row = slb + t * LB_STRIDE + half * 64;
        for (int i = 0; i < 64; i++) mx = fmaxf(mx, row[i]);
        mx = fmaxf(mx, __shfl_xor_sync(0xffffffffu, mx, 1));
        if (half == 0) { smB[t] = mx; g_mB[t0 + t] = mx; }
    }
    __syncthreads();

    for (int t = 0; t < 64; t++) {
        float eb = fexp_poly(slb[t * LB_STRIDE + s] - smB[t]);
        g_expB[(size_t)(t0 + t) * S + s] = eb;
    }
}

// ---------------- kernel 3: quad-stream linear scan, packed f32x2, 1 barrier/step ----
// Warp w owns columns [w*16, w*16+16); lane l = (col offset)<<1 | half.
// Thread holds E[half*64 + 2k..2k+1][j] packed in 32 b64 registers.
__global__ void __launch_bounds__(256, 2) scan_kernel(float* __restrict__ out) {
    __shared__ float swb[2][G][S];
    __shared__ float sbuf[2][G][PF * S];
    __shared__ float smb[2][G][PF];

    int tid = threadIdx.x;
    int w = tid >> 5, l = tid & 31;
    int j = w * 16 + (l >> 1);
    int half = l & 1;
    int srow = tid >> 5;              // staging row 0..7
    int scol = (tid & 31) * 4;        // staging col offset (4 floats = 16B)

    unsigned long long e2[32];
#pragma unroll
    for (int k = 0; k < 32; k++) {
        float lo = g_E[(half * 64 + 2 * k) * S + j];
        float hi = g_E[(half * 64 + 2 * k + 1) * S + j];
        PACK2(e2[k], lo, hi);
    }

    // per-stream geometry (int fits: all t < 2^31)
    int wstart[G], tbase[G], niter[G];
#pragma unroll
    for (int q = 0; q < G; q++) {
        int c = blockIdx.x + q * GRID;
        int ws = c * L;
        int we = ws + L; if (we > TT) we = TT;
        int t0 = (c == 0) ? 0 : (ws - W);
        int tstop = (c < CH - 1) ? (ws + L + 1) : we;
        int ni = tstop - (t0 + 1);
        if (ws >= TT) ni = 0;                 // dead chunk
        wstart[q] = ws; tbase[q] = t0 + 1; niter[q] = ni;
    }
    int maxiter = 0;
#pragma unroll
    for (int q = 0; q < G; q++) if (niter[q] > maxiter) maxiter = niter[q];

    float v[G], off[G];
#pragma unroll
    for (int q = 0; q < G; q++) {
        int t0 = tbase[q] - 1; if (t0 > TT - 1) t0 = TT - 1;
        if (blockIdx.x == 0 && q == 0) {
            v[q] = g_pstart[j] * g_expB[j];
            off[q] = g_mB[0];
            if (half == 0) { out[j] = v[q]; if (tid == 0) g_rl[0] = off[q]; }
        } else {
            v[q] = g_expB[(size_t)t0 * S + j];   // arbitrary start; forgotten in W steps
            off[q] = g_mB[t0];
        }
    }

    // preload staging block 0
#pragma unroll
    for (int q = 0; q < G; q++) {
        int tt = tbase[q] + srow; if (tt > TT - 1) tt = TT - 1;
        cp_async16(&sbuf[0][q][srow * S + scol], &g_expB[(size_t)tt * S + scol]);
    }
    if (tid < G * PF) {
        int q = tid >> 3, r = tid & 7;
        int c = blockIdx.x + q * GRID;
        int tb = ((c == 0) ? 0 : (c * L - W)) + 1;
        int t2 = tb + r; if (t2 > TT - 1) t2 = TT - 1;
        cp_async4(&smb[0][q][r], &g_mB[t2]);
    }
    cp_commit();
    cp_wait0();
    __syncthreads();

    for (int it = 0; it < maxiter; it++) {
        int blk = it >> 3;                 // PF = 8
        int phase = it & 7;
        int buf = it & 1;
        int cur = blk & 1;
        bool rn = (it & (NZ - 1)) == 0;

#pragma unroll
        for (int q = 0; q < G; q++)
            if (half == 0) swb[buf][q][j] = v[q];
        if (phase == PF - 1) cp_wait0();   // staged block blk+1 landed
        __syncthreads();                   // the ONLY barrier per step

        if (phase == 0) {                  // stage block blk+1 (7-step lead)
            int bb = (blk + 1) & 1;
#pragma unroll
            for (int q = 0; q < G; q++) {
                int tt = tbase[q] + (blk + 1) * PF + srow;
                if (tt > TT - 1) tt = TT - 1;
                cp_async16(&sbuf[bb][q][srow * S + scol], &g_expB[(size_t)tt * S + scol]);
            }
            if (tid < G * PF) {
                int q = tid >> 3, r = tid & 7;
                int c = blockIdx.x + q * GRID;
                int tb = ((c == 0) ? 0 : (c * L - W)) + 1;
                int t2 = tb + (blk + 1) * PF + r; if (t2 > TT - 1) t2 = TT - 1;
                cp_async4(&smb[bb][q][r], &g_mB[t2]);
            }
            cp_commit();
        }

        // dots: 2 stream-pairs, packed f32x2 over k-pairs
        float p[G];
#pragma unroll
        for (int qp = 0; qp < G; qp += 2) {
            const ulonglong2* sa = (const ulonglong2*)(&swb[buf][qp][half * 64]);
            const ulonglong2* sb = (const ulonglong2*)(&swb[buf][qp + 1][half * 64]);
            unsigned long long a0 = 0ULL, a1 = 0ULL, b0 = 0ULL, b1 = 0ULL;
#pragma unroll
            for (int k = 0; k < 16; k++) {
                ulonglong2 wa = sa[k];
                ulonglong2 wb = sb[k];
                FMA2(a0, wa.x, e2[2 * k],     a0);
                FMA2(a1, wa.y, e2[2 * k + 1], a1);
                FMA2(b0, wb.x, e2[2 * k],     b0);
                FMA2(b1, wb.y, e2[2 * k + 1], b1);
            }
            float a0l, a0h, a1l, a1h, b0l, b0h, b1l, b1h;
            UNPK2(a0l, a0h, a0); UNPK2(a1l, a1h, a1);
            UNPK2(b0l, b0h, b0); UNPK2(b1l, b1h, b1);
            p[qp]     = (a0l + a0h) + (a1l + a1h);
            p[qp + 1] = (b0l + b0h) + (b1l + b1h);
        }

        // renorm maxes (every NZ-th step; parallel re-read, off the serial chain)
        float mx[G];
        if (rn) {
#pragma unroll
            for (int q = 0; q < G; q++) {
                const float4* sf = (const float4*)(&swb[buf][q][half * 64]);
                float m0 = 0.f, m1 = 0.f;
#pragma unroll
                for (int k = 0; k < 16; k++) {
                    float4 x4 = sf[k];
                    m0 = fmaxf(m0, fmaxf(x4.x, x4.y));
                    m1 = fmaxf(m1, fmaxf(x4.z, x4.w));
                }
                mx[q] = fmaxf(m0, m1);
            }
        }

#pragma unroll
        for (int q = 0; q < G; q++) {
            p[q] += __shfl_xor_sync(0xffffffffu, p[q], 1);   // full 128-sum, both lanes
            float eb = sbuf[cur][q][phase * S + j];
            float mb = smb[cur][q][phase];
            float invM = 1.0f, logM = 0.0f;
            if (rn) {
                float M = fmaxf(mx[q], __shfl_xor_sync(0xffffffffu, mx[q], 1));
                invM = 1.0f / M;
                logM = __logf(M);
            }
            v[q] = p[q] * eb * invM;
            off[q] += mb + logM;
        }

        if (half == 0) {
#pragma unroll
            for (int q = 0; q < G; q++) {
                if (it < niter[q]) {
                    int t = tbase[q] + it;
                    int we = wstart[q] + L; if (we > TT) we = TT;
                    if (t >= wstart[q] && t < we) {
                        out[(size_t)t * S + j] = v[q];        // LINEAR; post pass converts
                        if (tid == 0) g_rl[t] = off[q];
                    } else if (t == wstart[q] + L) {
                        int c1 = blockIdx.x + q * GRID + 1;
                        g_junc[c1 * S + j] = v[q];
                        if (tid == 0) g_joff[c1] = off[q];
                    }
                }
            }
        }
    }
}

// ---------------- kernel 4a: per-junction offsets (linear lse diff) ----------------
__global__ void delta_local_kernel(const float* __restrict__ out) {
    int c = blockIdx.x + 1;          // 1..CH-1
    int j = threadIdx.x;             // 128
    __shared__ float s4[8];

    if ((long)c * L >= TT) {         // dead chunk: no correction
        if (j == 0) g_dloc[c] = 0.f;
        return;
    }

    float jv = g_junc[c * S + j];
    float ov = out[(size_t)c * L * S + j];

    float z = jv;
#pragma unroll
    for (int o = 16; o > 0; o >>= 1) z += __shfl_xor_sync(0xffffffffu, z, o);
    if ((j & 31) == 0) s4[j >> 5] = z;
    __syncthreads();
    float sum1 = s4[0] + s4[1] + s4[2] + s4[3];
    __syncthreads();

    z = ov;
#pragma unroll
    for (int o = 16; o > 0; o >>= 1) z += __shfl_xor_sync(0xffffffffu, z, o);
    if ((j & 31) == 0) s4[j >> 5] = z;
    __syncthreads();
    float sum2 = s4[0] + s4[1] + s4[2] + s4[3];

    if (j == 0)
        g_dloc[c] = (g_joff[c] + __logf(sum1)) - (g_rl[(size_t)c * L] + __logf(sum2));
}

// ---------------- kernel 4b: tiny prefix scan ----------------
__global__ void delta_scan_kernel() {
    if (threadIdx.x == 0) {
        float d = 0.f;
        g_delta[0] = 0.f;
        for (int c = 1; c < CH; c++) { d += g_dloc[c]; g_delta[c] = d; }
    }
}

// ---------------- kernel 5: fused log + offset + delta ----------------
__global__ void post_kernel(float* __restrict__ out) {
    size_t n4 = (size_t)TT * S / 4;
    size_t i4 = (size_t)blockIdx.x * blockDim.x + threadIdx.x;
    if (i4 >= n4) return;
    size_t e = i4 * 4;
    size_t t = e / S;
    int c = (int)(t / L);
    float add = g_rl[t] + g_delta[c];
    float4* p = (float4*)(out + e);
    float4 v = *p;
    v.x = flog_poly(v.x) + add;
    v.y = flog_poly(v.y) + add;
    v.z = flog_poly(v.z) + add;
    v.w = flog_poly(v.w) + add;
    *p = v;
}

// ---------------- kernel 6: final log-likelihood ----------------
__global__ void ll_kernel(float* __restrict__ out, int out_size) {
    int lane = threadIdx.x;  // 32
    const float* last = out + (size_t)(TT - 1) * S;
    float v0 = last[lane], v1 = last[lane + 32], v2 = last[lane + 64], v3 = last[lane + 96];
    float m = fmaxf(fmaxf(v0, v1), fmaxf(v2, v3));
    for (int o = 16; o > 0; o >>= 1) m = fmaxf(m, __shfl_xor_sync(0xffffffffu, m, o));
    float s = __expf(v0 - m) + __expf(v1 - m) + __expf(v2 - m) + __expf(v3 - m);
    for (int o = 16; o > 0; o >>= 1) s += __shfl_xor_sync(0xffffffffu, s, o);
    if (lane == 0 && out_size > TT * S) out[(size_t)TT * S] = m + __logf(s);
}

// ---------------- launch ----------------
extern "C" void kernel_launch(void* const* d_in, const int* in_sizes, int n_in,
                              void* d_out, int out_size) {
    const float* x          = (const float*)d_in[0];
    const float* start_prob = (const float*)d_in[1];
    const float* trans      = (const float*)d_in[2];
    const float* means      = (const float*)d_in[3];
    const float* vars       = (const float*)d_in[4];
    float* out = (float*)d_out;

    prep_kernel<<<1, 128>>>(start_prob, trans, means, vars);
    logb_kernel<<<TT / 64, 128>>>(x);
    scan_kernel<<<GRID, 256>>>(out);
    delta_local_kernel<<<CH - 1, 128>>>(out);
    delta_scan_kernel<<<1, 32>>>();
    size_t n4 = (size_t)TT * S / 4;
    post_kernel<<<(unsigned)((n4 + 255) / 256), 256>>>(out);
    ll_kernel<<<1, 32>>>(out, out_size);
}

// round 15
// speedup vs baseline: 3.8039x; 3.8039x over previous
#include <cuda_runtime.h>
#include <math.h>
#include <stdint.h>

#define TT 262144
#define S 128
#define F 16
#define CH 592
#define GRID 296        // CTAs; each runs streams c and c+GRID
#define L 443           // 592 * 443 = 262256 >= TT
#define W 64            // warmup steps (forgetting window)
#define NZ 4            // renormalize every NZ steps
#define PF 16           // staged rows per block

// ---------------- scratch (device globals; no allocation allowed) ----------------
__device__ float g_expB[(size_t)TT * S];       // exp(logB - mB) per row, 134 MB
__device__ float g_mB[TT];                     // per-row max of logB
__device__ float g_E[S * S];                   // row-stochastic softmax(trans)
__device__ float g_pstart[S];                  // exp(log_softmax(start))
__device__ float g_iv[S * F];
__device__ float g_m2[S * F];
__device__ float g_cst[S];
__device__ float g_junc[CH * S];               // linear junction vectors
__device__ float g_joff[CH];                   // offsets at junctions
__device__ float g_rl[TT];                     // per-row accumulated offset (chunk frame)
__device__ float g_dloc[CH];
__device__ float g_delta[CH];

// ---------------- packed f32x2 + cp.async helpers ----------------
#define FMA2(d, a, b, c) \
    asm("fma.rn.f32x2 %0, %1, %2, %3;" : "=l"(d) : "l"(a), "l"(b), "l"(c))
#define PACK2(d, lo, hi) \
    asm("mov.b64 %0, {%1, %2};" : "=l"(d) : "f"(lo), "f"(hi))
#define UNPK2(lo, hi, p) \
    asm("mov.b64 {%0, %1}, %2;" : "=f"(lo), "=f"(hi) : "l"(p))

__device__ __forceinline__ void cp_async16(void* smem_dst, const void* gmem_src) {
    unsigned sa = (unsigned)__cvta_generic_to_shared(smem_dst);
    asm volatile("cp.async.cg.shared.global [%0], [%1], 16;" :: "r"(sa), "l"(gmem_src));
}
__device__ __forceinline__ void cp_async4(void* smem_dst, const void* gmem_src) {
    unsigned sa = (unsigned)__cvta_generic_to_shared(smem_dst);
    asm volatile("cp.async.ca.shared.global [%0], [%1], 4;" :: "r"(sa), "l"(gmem_src));
}
__device__ __forceinline__ void cp_commit() { asm volatile("cp.async.commit_group;"); }
__device__ __forceinline__ void cp_wait0()  { asm volatile("cp.async.wait_group 0;"); }

// ---------------- fast math (FMA polys; no MUFU) ----------------
__device__ __forceinline__ float fexp_poly(float x) {
    x = fmaxf(x, -80.0f);
    float y = x * 1.44269504f;
    float n = rintf(y);
    float t = (y - n) * 0.69314718f;
    float p = 1.0f / 720.0f;
    p = fmaf(p, t, 1.0f / 120.0f);
    p = fmaf(p, t, 1.0f / 24.0f);
    p = fmaf(p, t, 1.0f / 6.0f);
    p = fmaf(p, t, 0.5f);
    p = fmaf(p, t, 1.0f);
    p = fmaf(p, t, 1.0f);
    return p * __int_as_float(((int)n + 127) << 23);
}

__device__ __forceinline__ float flog_poly(float v) {
    v = fmaxf(v, 1e-38f);
    int b = __float_as_int(v);
    int e = ((b >> 23) & 255) - 127;
    float m = __int_as_float((b & 0x007fffff) | 0x3f800000);  // [1,2)
    if (m > 1.41421356f) { m *= 0.5f; e += 1; }
    float r = m - 1.0f;
    float p = -1.0f / 12.0f;
    p = fmaf(p, r,  1.0f / 11.0f);
    p = fmaf(p, r, -1.0f / 10.0f);
    p = fmaf(p, r,  1.0f / 9.0f);
    p = fmaf(p, r, -1.0f / 8.0f);
    p = fmaf(p, r,  1.0f / 7.0f);
    p = fmaf(p, r, -1.0f / 6.0f);
    p = fmaf(p, r,  1.0f / 5.0f);
    p = fmaf(p, r, -0.25f);
    p = fmaf(p, r,  1.0f / 3.0f);
    p = fmaf(p, r, -0.5f);
    p = fmaf(p, r,  1.0f);
    return fmaf((float)e, 0.69314718f, r * p);
}

// ---------------- kernel 1: small preprocessing ----------------
__global__ void prep_kernel(const float* __restrict__ start_prob,
                            const float* __restrict__ trans,
                            const float* __restrict__ means,
                            const float* __restrict__ vars) {
    int s = threadIdx.x;  // 128 threads
    __shared__ float red[S];

    float sp = start_prob[s];
    red[s] = sp; __syncthreads();
    for (int o = 64; o > 0; o >>= 1) { if (s < o) red[s] = fmaxf(red[s], red[s + o]); __syncthreads(); }
    float mx = red[0]; __syncthreads();
    red[s] = expf(sp - mx); __syncthreads();
    for (int o = 64; o > 0; o >>= 1) { if (s < o) red[s] += red[s + o]; __syncthreads(); }
    float lse = mx + logf(red[0]);
    g_pstart[s] = expf(sp - lse);

    float m = -INFINITY;
    for (int j = 0; j < S; j++) m = fmaxf(m, trans[s * S + j]);
    float z = 0.f;
    for (int j = 0; j < S; j++) z += expf(trans[s * S + j] - m);
    float inv = 1.0f / z;
    for (int j = 0; j < S; j++) g_E[s * S + j] = expf(trans[s * S + j] - m) * inv;

    float ln = 0.f, c2 = 0.f;
    for (int f = 0; f < F; f++) {
        float v = vars[s * F + f];
        v = fmaxf(v, 1e-6f);
        float iv = 1.0f / v;
        float mu = means[s * F + f];
        g_iv[s * F + f] = iv;
        g_m2[s * F + f] = 2.0f * mu * iv;
        ln += logf(6.2831853071795864f * v);
        c2 += mu * mu * iv;
    }
    g_cst[s] = -0.5f * (ln + c2);
}

// ---------------- kernel 2: emissions -> expB + mB ----------------
#define LB_STRIDE 130
__global__ void logb_kernel(const float* __restrict__ x) {
    int s = threadIdx.x;             // 128 threads (= states)
    int t0 = blockIdx.x * 64;        // 64 timesteps per block
    __shared__ float sx[64 * F];
    __shared__ float slb[64 * LB_STRIDE];
    __shared__ float smB[64];

    for (int i = s; i < 64 * F; i += S) sx[i] = x[(size_t)t0 * F + i];
    float iv[F], m2[F];
#pragma unroll
    for (int f = 0; f < F; f++) { iv[f] = g_iv[s * F + f]; m2[f] = g_m2[s * F + f]; }
    float cst = g_cst[s];
    __syncthreads();

    for (int t = 0; t < 64; t++) {
        float q = 0.f;
#pragma unroll
        for (int f = 0; f < F; f++) {
            float xv = sx[t * F + f];
            q = fmaf(xv, fmaf(xv, iv[f], -m2[f]), q);
        }
        slb[t * LB_STRIDE + s] = cst - 0.5f * q;
    }
    __syncthreads();

    {
        int t = s >> 1, half = s & 1;
        float mx = -INFINITY;
        const float* row = slb + t * LB_STRIDE + half * 64;
        for (int i = 0; i < 64; i++) mx = fmaxf(mx, row[i]);
        mx = fmaxf(mx, __shfl_xor_sync(0xffffffffu, mx, 1));
        if (half == 0) { smB[t] = mx; g_mB[t0 + t] = mx; }
    }
    __syncthreads();

    for (int t = 0; t < 64; t++) {
        float eb = fexp_poly(slb[t * LB_STRIDE + s] - smB[t]);
        g_expB[(size_t)(t0 + t) * S + s] = eb;
    }
}

// ---------------- kernel 3: dual-stream linear scan, packed f32x2 dot --------------
// Each CTA runs TWO independent chunk recursions (c, c+GRID) sharing the same
// register-resident packed E and the same per-step barrier.
// Warp w owns columns [w*16, w*16+16); lane l = (col offset)<<1 | half.
__global__ void __launch_bounds__(256, 2) scan_kernel(float* __restrict__ out) {
    __shared__ float swA[2][S], swB[2][S];
    __shared__ float sbufA[2][PF * S], sbufB[2][PF * S];
    __shared__ float smbA[2][PF], smbB[2][PF];

    int tid = threadIdx.x;
    int w = tid >> 5, l = tid & 31;
    int j = w * 16 + (l >> 1);
    int half = l & 1;
    int cA = blockIdx.x;
    int cB = blockIdx.x + GRID;
    int srow = tid >> 4;              // staging row 0..15
    int scol = (tid & 15) * 8;        // staging col offset (8 floats = 32B)

    // packed E column slice: e2[k] = (E[half*64+2k][j], E[half*64+2k+1][j])
    unsigned long long e2[32];
#pragma unroll
    for (int k = 0; k < 32; k++) {
        float lo = g_E[(half * 64 + 2 * k) * S + j];
        float hi = g_E[(half * 64 + 2 * k + 1) * S + j];
        PACK2(e2[k], lo, hi);
    }

    // stream A geometry
    long wstartA = (long)cA * L;
    long wendA = wstartA + L; if (wendA > TT) wendA = TT;
    long t0A = (cA == 0) ? 0 : (wstartA - W);
    long tstopA = (cA < CH - 1) ? (wstartA + L + 1) : wendA;
    long tbaseA = t0A + 1;
    int niterA = (int)(tstopA - tbaseA);
    // stream B geometry
    long wstartB = (long)cB * L;
    long wendB = wstartB + L; if (wendB > TT) wendB = TT;
    long t0B = wstartB - W;
    long tstopB = (cB < CH - 1) ? (wstartB + L + 1) : wendB;
    long tbaseB = t0B + 1;
    int niterB = (int)(tstopB - tbaseB);

    int maxiter = niterA > niterB ? niterA : niterB;

    float vA, offA, vB, offB;
    if (cA == 0) {
        vA = g_pstart[j] * g_expB[j];
        offA = g_mB[0];
        if (half == 0) { out[j] = vA; if (tid == 0) g_rl[0] = offA; }
    } else {
        vA = g_expB[(size_t)t0A * S + j];
        offA = g_mB[t0A];
    }
    vB = g_expB[(size_t)t0B * S + j];
    offB = g_mB[t0B];

    // preload staging block 0 for both streams
    {
        long ta = tbaseA + srow; if (ta > TT - 1) ta = TT - 1;
        long tb = tbaseB + srow; if (tb > TT - 1) tb = TT - 1;
        cp_async16(&sbufA[0][srow * S + scol],     &g_expB[ta * S + scol]);
        cp_async16(&sbufA[0][srow * S + scol + 4], &g_expB[ta * S + scol + 4]);
        cp_async16(&sbufB[0][srow * S + scol],     &g_expB[tb * S + scol]);
        cp_async16(&sbufB[0][srow * S + scol + 4], &g_expB[tb * S + scol + 4]);
        if (tid < PF) {
            long ta2 = tbaseA + tid; if (ta2 > TT - 1) ta2 = TT - 1;
            long tb2 = tbaseB + tid; if (tb2 > TT - 1) tb2 = TT - 1;
            cp_async4(&smbA[0][tid], &g_mB[ta2]);
            cp_async4(&smbB[0][tid], &g_mB[tb2]);
        }
        cp_commit();
        cp_wait0();
    }
    __syncthreads();

    for (int it = 0; it < maxiter; it++) {
        int blk = it >> 4;
        int phase = it & 15;
        int buf = it & 1;
        bool rn = (it & (NZ - 1)) == 0;

        if (half == 0) { swA[buf][j] = vA; swB[buf][j] = vB; }
        if (phase == 15) cp_wait0();        // staged block blk+1 landed
        __syncthreads();                    // the ONLY barrier per step

        if (phase == 0) {                   // stage block blk+1 for both streams
            int bb = (blk + 1) & 1;
            long ta = tbaseA + (long)(blk + 1) * PF + srow; if (ta > TT - 1) ta = TT - 1;
            long tb = tbaseB + (long)(blk + 1) * PF + srow; if (tb > TT - 1) tb = TT - 1;
            cp_async16(&sbufA[bb][srow * S + scol],     &g_expB[ta * S + scol]);
            cp_async16(&sbufA[bb][srow * S + scol + 4], &g_expB[ta * S + scol + 4]);
            cp_async16(&sbufB[bb][srow * S + scol],     &g_expB[tb * S + scol]);
            cp_async16(&sbufB[bb][srow * S + scol + 4], &g_expB[tb * S + scol + 4]);
            if (tid < PF) {
                long ta2 = tbaseA + (long)(blk + 1) * PF + tid; if (ta2 > TT - 1) ta2 = TT - 1;
                long tb2 = tbaseB + (long)(blk + 1) * PF + tid; if (tb2 > TT - 1) tb2 = TT - 1;
                cp_async4(&smbA[(blk + 1) & 1][tid], &g_mB[ta2]);
                cp_async4(&smbB[(blk + 1) & 1][tid], &g_mB[tb2]);
            }
            cp_commit();
        }

        float ebA = sbufA[blk & 1][phase * S + j];
        float mbA = smbA[blk & 1][phase];
        float ebB = sbufB[blk & 1][phase * S + j];
        float mbB = smbB[blk & 1][phase];

        // two packed dots over my 64 rows (fma.rn.f32x2: 2 MACs/inst)
        const ulonglong2* a4 = (const ulonglong2*)(&swA[buf][half * 64]);
        const ulonglong2* b4 = (const ulonglong2*)(&swB[buf][half * 64]);
        unsigned long long pa0 = 0ULL, pa1 = 0ULL, pb0 = 0ULL, pb1 = 0ULL;
        float ma = 0.f, mb_ = 0.f;
#pragma unroll
        for (int k = 0; k < 16; k++) {
            ulonglong2 qa = a4[k];
            ulonglong2 qb = b4[k];
            FMA2(pa0, qa.x, e2[2 * k],     pa0);
            FMA2(pa1, qa.y, e2[2 * k + 1], pa1);
            FMA2(pb0, qb.x, e2[2 * k],     pb0);
            FMA2(pb1, qb.y, e2[2 * k + 1], pb1);
            if (rn) {
                float x0, x1, x2, x3;
                UNPK2(x0, x1, qa.x); UNPK2(x2, x3, qa.y);
                ma = fmaxf(ma, fmaxf(fmaxf(x0, x1), fmaxf(x2, x3)));
                UNPK2(x0, x1, qb.x); UNPK2(x2, x3, qb.y);
                mb_ = fmaxf(mb_, fmaxf(fmaxf(x0, x1), fmaxf(x2, x3)));
            }
        }
        float a0l, a0h, a1l, a1h, b0l, b0h, b1l, b1h;
        UNPK2(a0l, a0h, pa0); UNPK2(a1l, a1h, pa1);
        UNPK2(b0l, b0h, pb0); UNPK2(b1l, b1h, pb1);
        float pA = (a0l + a0h) + (a1l + a1h);
        float pB = (b0l + b0h) + (b1l + b1h);
        pA += __shfl_xor_sync(0xffffffffu, pA, 1);
        pB += __shfl_xor_sync(0xffffffffu, pB, 1);

        float invA = 1.0f, logA = 0.0f, invB = 1.0f, logB = 0.0f;
        if (rn) {
            float MA = fmaxf(ma, __shfl_xor_sync(0xffffffffu, ma, 1));
            float MB = fmaxf(mb_, __shfl_xor_sync(0xffffffffu, mb_, 1));
            invA = 1.0f / MA; logA = __logf(MA);
            invB = 1.0f / MB; logB = __logf(MB);
        }

        vA = pA * ebA * invA;
        offA += mbA + logA;
        vB = pB * ebB * invB;
        offB += mbB + logB;

        if (half == 0) {
            if (it < niterA) {
                long t = tbaseA + it;
                if (t >= wstartA && t < wendA) {
                    out[(size_t)t * S + j] = vA;
                    if (tid == 0) g_rl[t] = offA;
                } else if (t == wstartA + L) {
                    g_junc[(cA + 1) * S + j] = vA;
                    if (tid == 0) g_joff[cA + 1] = offA;
                }
            }
            if (it < niterB) {
                long t = tbaseB + it;
                if (t >= wstartB && t < wendB) {
                    out[(size_t)t * S + j] = vB;
                    if (tid == 0) g_rl[t] = offB;
                } else if (t == wstartB + L) {
                    g_junc[(cB + 1) * S + j] = vB;
                    if (tid == 0) g_joff[cB + 1] = offB;
                }
            }
        }
    }
}

// ---------------- kernel 4a: per-junction offsets (linear lse diff) ----------------
__global__ void delta_local_kernel(const float* __restrict__ out) {
    int c = blockIdx.x + 1;          // 1..CH-1
    int j = threadIdx.x;             // 128
    __shared__ float s4[8];

    float jv = g_junc[c * S + j];
    float ov = out[(size_t)c * L * S + j];

    float z = jv;
#pragma unroll
    for (int o = 16; o > 0; o >>= 1) z += __shfl_xor_sync(0xffffffffu, z, o);
    if ((j & 31) == 0) s4[j >> 5] = z;
    __syncthreads();
    float sum1 = s4[0] + s4[1] + s4[2] + s4[3];
    __syncthreads();

    z = ov;
#pragma unroll
    for (int o = 16; o > 0; o >>= 1) z += __shfl_xor_sync(0xffffffffu, z, o);
    if ((j & 31) == 0) s4[j >> 5] = z;
    __syncthreads();
    float sum2 = s4[0] + s4[1] + s4[2] + s4[3];

    if (j == 0)
        g_dloc[c] = (g_joff[c] + __logf(sum1)) - (g_rl[(size_t)c * L] + __logf(sum2));
}

// ---------------- kernel 4b: tiny prefix scan ----------------
__global__ void delta_scan_kernel() {
    if (threadIdx.x == 0) {
        float d = 0.f;
        g_delta[0] = 0.f;
        for (int c = 1; c < CH; c++) { d += g_dloc[c]; g_delta[c] = d; }
    }
}

// ---------------- kernel 5: fused log + offset + delta ----------------
__global__ void post_kernel(float* __restrict__ out) {
    size_t n4 = (size_t)TT * S / 4;
    size_t i4 = (size_t)blockIdx.x * blockDim.x + threadIdx.x;
    if (i4 >= n4) return;
    size_t e = i4 * 4;
    size_t t = e / S;
    int c = (int)(t / L);
    float add = g_rl[t] + g_delta[c];
    float4* p = (float4*)(out + e);
    float4 v = *p;
    v.x = flog_poly(v.x) + add;
    v.y = flog_poly(v.y) + add;
    v.z = flog_poly(v.z) + add;
    v.w = flog_poly(v.w) + add;
    *p = v;
}

// ---------------- kernel 6: final log-likelihood ----------------
__global__ void ll_kernel(float* __restrict__ out, int out_size) {
    int lane = threadIdx.x;  // 32
    const float* last = out + (size_t)(TT - 1) * S;
    float v0 = last[lane], v1 = last[lane + 32], v2 = last[lane + 64], v3 = last[lane + 96];
    float m = fmaxf(fmaxf(v0, v1), fmaxf(v2, v3));
    for (int o = 16; o > 0; o >>= 1) m = fmaxf(m, __shfl_xor_sync(0xffffffffu, m, o));
    float s = __expf(v0 - m) + __expf(v1 - m) + __expf(v2 - m) + __expf(v3 - m);
    for (int o = 16; o > 0; o >>= 1) s += __shfl_xor_sync(0xffffffffu, s, o);
    if (lane == 0 && out_size > TT * S) out[(size_t)TT * S] = m + __logf(s);
}

// ---------------- launch ----------------
extern "C" void kernel_launch(void* const* d_in, const int* in_sizes, int n_in,
                              void* d_out, int out_size) {
    const float* x          = (const float*)d_in[0];
    const float* start_prob = (const float*)d_in[1];
    const float* trans      = (const float*)d_in[2];
    const float* means      = (const float*)d_in[3];
    const float* vars       = (const float*)d_in[4];
    float* out = (float*)d_out;

    prep_kernel<<<1, 128>>>(start_prob, trans, means, vars);
    logb_kernel<<<TT / 64, 128>>>(x);
    scan_kernel<<<GRID, 256>>>(out);
    delta_local_kernel<<<CH - 1, 128>>>(out);
    delta_scan_kernel<<<1, 32>>>();
    size_t n4 = (size_t)TT * S / 4;
    post_kernel<<<(unsigned)((n4 + 255) / 256), 256>>>(out);
    ll_kernel<<<1, 32>>>(out, out_size);
}